// round 17
// baseline (speedup 1.0000x reference)
#include <cuda_runtime.h>

// ---------------------------------------------------------------------------
// MWDLSTMGCT: only the low-pass wavelet chain + LSTM-3 affect the output.
//   xl1 = avgpool2(sigmoid(x @ W1L^T + b1L))        (256 x 512)
//   xl2 = avgpool2(sigmoid(xl1 @ W2L^T + b2L))      (256 x 256)
//   h   = LSTM(xl2 as scalar sequence; Wih3,Whh3,b3), final hidden (256 x 100)
//   out = h @ Wout^T + bout                          (256 x 1)
// ---------------------------------------------------------------------------

#define NBATCH 256
#define HID    100
#define GATES  400   // 4*HID
#define TSTEPS 256
#define ZSTR   104   // z-array stride per gate type (bank-conflict-free quad reads)

__device__ __align__(16) float g_xl1[256 * 512];
__device__ __align__(16) float g_xl2[256 * 256];

__device__ __forceinline__ float sigf(float x) { return 1.f / (1.f + __expf(-x)); }
// tanh(x) = 1 - 2/(exp(2x)+1); exact saturation.
__device__ __forceinline__ float tanh_fast(float x) {
    return 1.f - 2.f / (__expf(2.f * x) + 1.f);
}

// ---------------------------------------------------------------------------
// Fused GEMM (C = A @ W^T), bias, sigmoid, avgpool2 along N.  (R14, proven)
// Tile 32(M) x 64(N), K-slices of 32, double-buffered smem, 256 threads,
// microtile 4x2, conflict-free padded staging, register-rotated kk loop.
// ---------------------------------------------------------------------------
#define APAD 36
#define BPAD 66

template <int K>
__device__ __forceinline__ void gemm_sig_pool_body(
    const float* __restrict__ A, const float* __restrict__ W,
    const float* __restrict__ bias, float* __restrict__ out, int halfN)
{
    __shared__ __align__(16) float As[2][32 * APAD];
    __shared__ __align__(16) float Bs[2][32 * BPAD];

    const int m0 = blockIdx.y * 32;
    const int n0 = blockIdx.x * 64;
    const int tid = threadIdx.x;

    const int lmB = tid >> 2;
    const int lkB = (tid & 3) * 4;
    const float* Bg = W + (n0 + lmB) * K + lkB;
    const bool hasA = tid < 128;
    const int lmA = (tid & 127) >> 2;
    const int lkA = (tid & 3) * 4;
    const float* Ag = A + (m0 + lmA) * K + lkA;

    const int tx = tid & 31;
    const int ty = tid >> 5;

    float acc[4][2] = {};
    const int NT = K / 32;

    float4 aLo, aHi, bLo, bHi;
    auto ldg = [&](int s) {
        bLo = *(const float4*)(Bg + s * 32);
        bHi = *(const float4*)(Bg + s * 32 + 16);
        if (hasA) {
            aLo = *(const float4*)(Ag + s * 32);
            aHi = *(const float4*)(Ag + s * 32 + 16);
        }
    };
    auto stage = [&](int buf) {
        float* Bd = &Bs[buf][0];
        Bd[(lkB + 0) * BPAD + lmB] = bLo.x;
        Bd[(lkB + 1) * BPAD + lmB] = bLo.y;
        Bd[(lkB + 2) * BPAD + lmB] = bLo.z;
        Bd[(lkB + 3) * BPAD + lmB] = bLo.w;
        Bd[(lkB + 16) * BPAD + lmB] = bHi.x;
        Bd[(lkB + 17) * BPAD + lmB] = bHi.y;
        Bd[(lkB + 18) * BPAD + lmB] = bHi.z;
        Bd[(lkB + 19) * BPAD + lmB] = bHi.w;
        if (hasA) {
            float* Ad = &As[buf][0];
            Ad[(lkA + 0) * APAD + lmA] = aLo.x;
            Ad[(lkA + 1) * APAD + lmA] = aLo.y;
            Ad[(lkA + 2) * APAD + lmA] = aLo.z;
            Ad[(lkA + 3) * APAD + lmA] = aLo.w;
            Ad[(lkA + 16) * APAD + lmA] = aHi.x;
            Ad[(lkA + 17) * APAD + lmA] = aHi.y;
            Ad[(lkA + 18) * APAD + lmA] = aHi.z;
            Ad[(lkA + 19) * APAD + lmA] = aHi.w;
        }
    };
    auto compute = [&](int buf) {
        const float* Ab = &As[buf][ty * 4];
        const float* Bb = &Bs[buf][tx * 2];
        float4 av = *(const float4*)(Ab);
        float2 bv = *(const float2*)(Bb);
        #pragma unroll
        for (int kk = 0; kk < 32; kk++) {
            float4 avn = av; float2 bvn = bv;
            if (kk < 31) {
                avn = *(const float4*)(Ab + (kk + 1) * APAD);
                bvn = *(const float2*)(Bb + (kk + 1) * BPAD);
            }
            acc[0][0] = fmaf(av.x, bv.x, acc[0][0]);
            acc[0][1] = fmaf(av.x, bv.y, acc[0][1]);
            acc[1][0] = fmaf(av.y, bv.x, acc[1][0]);
            acc[1][1] = fmaf(av.y, bv.y, acc[1][1]);
            acc[2][0] = fmaf(av.z, bv.x, acc[2][0]);
            acc[2][1] = fmaf(av.z, bv.y, acc[2][1]);
            acc[3][0] = fmaf(av.w, bv.x, acc[3][0]);
            acc[3][1] = fmaf(av.w, bv.y, acc[3][1]);
            av = avn; bv = bvn;
        }
    };

    ldg(0);
    stage(0);
    __syncthreads();

    for (int tI = 0; tI < NT; tI++) {
        if (tI + 1 < NT) ldg(tI + 1);
        compute(tI & 1);
        if (tI + 1 < NT) {
            stage((tI & 1) ^ 1);
            __syncthreads();
        }
    }

    const float bn0 = bias[n0 + tx * 2 + 0];
    const float bn1 = bias[n0 + tx * 2 + 1];
    const int ocol = (n0 >> 1) + tx;
    #pragma unroll
    for (int i = 0; i < 4; i++) {
        const int m = m0 + ty * 4 + i;
        float s0 = sigf(acc[i][0] + bn0);
        float s1 = sigf(acc[i][1] + bn1);
        out[m * halfN + ocol] = 0.5f * (s0 + s1);
    }
}

__global__ void __launch_bounds__(256) gemm1_kernel(
    const float* __restrict__ A, const float* __restrict__ W,
    const float* __restrict__ bias)
{
    gemm_sig_pool_body<1024>(A, W, bias, g_xl1, 512);
}

__global__ void __launch_bounds__(256) gemm2_kernel(
    const float* __restrict__ W, const float* __restrict__ bias)
{
    gemm_sig_pool_body<512>(g_xl1, W, bias, g_xl2, 256);
}

// ---------------------------------------------------------------------------
// LSTM-3: persistent per-CTA, 2 batch rows per CTA, SMSP-BALANCED split-K
// gate GEMV + quad-parallel epilogue. 896 threads = 28 warps (7/SMSP):
//   Warps 0..23 (t<768): gates 0..383 as (gate, K-half) tasks:
//     t<384 -> half-A (k 0..49, + wih*x+b), t in [384,768) -> half-B
//     (k 50..99, wih=b=0). 100 FFMA/thread/step.
//   Warps 24..27 (t in [768,896)): gates 384..399 as (gate, K-quarter, row)
//     tasks: 16 gates x 4 quarters x 2 rows = 128 tasks of 25 FFMA. One such
//     warp per SMSP -> per-SMSP gate issue = 6*100 + 25 = 625 warp-FFMA,
//     exactly the 1250-cyc floor on every SMSP.
// z combine: gates 0..383 -> zA+zB (stride ZSTR); gates 384..399 (type-3,
// units 84..99) -> 4 partials in zQ[row][kq][16].
// Epilogue: threads 0..799, q=t&3 gate type, uu=t>>2 (row,unit); one
// transcendental per lane, combined via 3 shfl_xor; lane q=0 owns c.
// ---------------------------------------------------------------------------
__global__ void __launch_bounds__(896, 1) lstm_kernel(
    const float* __restrict__ Wih, const float* __restrict__ Whh,
    const float* __restrict__ b3,  const float* __restrict__ Wout,
    const float* __restrict__ bout, float* __restrict__ out)
{
    const int r0 = blockIdx.x * 2;
    const int t = threadIdx.x;

    __shared__ __align__(8) float2 h_s[HID];
    __shared__ float zA[2][4 * ZSTR];
    __shared__ float zB[2][4 * ZSTR];
    __shared__ float zQ[2][4][16];
    __shared__ float x_s[2][TSTEPS];
    __shared__ float red0[HID], red1[HID];

    const bool isMain = t < 768;

    float wreg[50];
    float wih_g = 0.f, bg = 0.f;
    float* zdst0;
    float* zdst1;
    int qrow = 0;      // quarter-task row
    int qkb = 0;       // quarter-task k base

    if (isMain) {
        const bool halfA = t < 384;
        const int g = halfA ? t : t - 384;            // 0..383
        const int kb = halfA ? 0 : 50;
        const float* wrow = Whh + g * HID + kb;
        #pragma unroll
        for (int k = 0; k < 50; k += 2) {
            float2 w = *(const float2*)(wrow + k);
            wreg[k] = w.x; wreg[k + 1] = w.y;
        }
        if (halfA) { wih_g = Wih[g]; bg = b3[g]; }
        const int zoff = (g / 100) * ZSTR + (g % 100);
        zdst0 = halfA ? &zA[0][zoff] : &zB[0][zoff];
        zdst1 = halfA ? &zA[1][zoff] : &zB[1][zoff];
        // store kb in qkb for the h-pointer base (reused below)
        qkb = kb;
    } else {
        const int idx = t - 768;                       // 0..127
        const int u = idx & 15;                        // gate unit 84+u? -> gate 384+u
        const int kq = (idx >> 4) & 3;                 // K quarter
        qrow = idx >> 6;                               // row 0/1
        const int g = 384 + u;
        qkb = kq * 25;
        const float* wrow = Whh + g * HID + qkb;
        #pragma unroll
        for (int k = 0; k < 25; k++) wreg[k] = wrow[k];
        if (kq == 0) { wih_g = Wih[g]; bg = b3[g]; }
        zdst0 = &zQ[qrow][kq][u];
        zdst1 = zdst0;                                 // unused second store slot
    }

    if (t < TSTEPS) {
        x_s[0][t] = g_xl2[r0 * TSTEPS + t];
        x_s[1][t] = g_xl2[(r0 + 1) * TSTEPS + t];
    }
    if (t < HID) h_s[t] = make_float2(0.f, 0.f);

    // Epilogue mapping: q = gate type, uu = (row, unit).
    const int q = t & 3;
    const int uu = t >> 2;                 // 0..199 (valid for t<800)
    const int erow = (uu >= HID) ? 1 : 0;
    const int ej = uu - erow * HID;        // 0..99
    const int zread = q * ZSTR + ej;
    const bool isG = (q == 2);
    const bool special = (q == 3) && (ej >= 84);   // 4-partial gates
    float c_st = 0.f;
    __syncthreads();

    for (int step = 0; step < TSTEPS; step++) {
        // ---- gate phase ----
        if (isMain) {
            float z0 = fmaf(wih_g, x_s[0][step], bg);
            float z1 = fmaf(wih_g, x_s[1][step], bg);
            const float2* hp = &h_s[qkb];
            #pragma unroll
            for (int k = 0; k < 50; k++) {
                float2 h = hp[k];
                z0 = fmaf(wreg[k], h.x, z0);
                z1 = fmaf(wreg[k], h.y, z1);
            }
            *zdst0 = z0;
            *zdst1 = z1;
        } else {
            float zq = fmaf(wih_g, x_s[qrow][step], bg);
            const float* hp = ((const float*)h_s) + 2 * qkb + qrow;
            #pragma unroll
            for (int k = 0; k < 25; k++)
                zq = fmaf(wreg[k], hp[2 * k], zq);
            *zdst0 = zq;
        }
        __syncthreads();
        // ---- epilogue: quad-parallel transcendentals + shuffle combine ----
        if (t < 800) {
            float zq;
            if (special) {
                zq = zQ[erow][0][ej - 84] + zQ[erow][1][ej - 84]
                   + zQ[erow][2][ej - 84] + zQ[erow][3][ej - 84];
            } else {
                zq = zA[erow][zread] + zB[erow][zread];
            }
            float xin = isG ? 2.f * zq : zq;
            float s = sigf(xin);
            float v = isG ? 2.f * s - 1.f : s;      // q: 0->sig(i) 1->sig(f) 2->tanh(g) 3->sig(o)
            float w  = __shfl_xor_sync(0xFFFFFFFFu, v, 1);
            float u2 = __shfl_xor_sync(0xFFFFFFFFu, v, 2);
            float u3 = __shfl_xor_sync(0xFFFFFFFFu, w, 2);
            if (q == 0) {
                c_st = w * c_st + v * u2;
                float h = u3 * tanh_fast(c_st);
                ((float*)&h_s[ej])[erow] = h;
            }
        }
        __syncthreads();
    }

    // Final projection: out[r] = h_final . Wout + bout
    if (t < HID) {
        float w = Wout[t];
        red0[t] = h_s[t].x * w;
        red1[t] = h_s[t].y * w;
    }
    __syncthreads();
    if (t == 0) {
        float s = bout[0];
        for (int k = 0; k < HID; k++) s += red0[k];
        out[r0] = s;
    }
    if (t == 1) {
        float s = bout[0];
        for (int k = 0; k < HID; k++) s += red1[k];
        out[r0 + 1] = s;
    }
}

// ---------------------------------------------------------------------------
// Launch. Input order (metadata.txt): x, W1H, b1H, W1L, b1L, W2H, b2H, W2L,
// b2L, Wih1, Whh1, b1, Wih2, Whh2, b2, Wih3, Whh3, b3, Wout, bout.
// Only the low-pass + LSTM-3 inputs are used.
// ---------------------------------------------------------------------------
extern "C" void kernel_launch(void* const* d_in, const int* in_sizes, int n_in,
                              void* d_out, int out_size)
{
    const float* x    = (const float*)d_in[0];
    const float* W1L  = (const float*)d_in[3];
    const float* b1L  = (const float*)d_in[4];
    const float* W2L  = (const float*)d_in[7];
    const float* b2L  = (const float*)d_in[8];
    const float* Wih3 = (const float*)d_in[15];
    const float* Whh3 = (const float*)d_in[16];
    const float* b3   = (const float*)d_in[17];
    const float* Wout = (const float*)d_in[18];
    const float* bout = (const float*)d_in[19];
    float* out = (float*)d_out;

    dim3 grid1(16, 8);   // N=1024/64, M=256/32 -> 128 CTAs
    dim3 grid2(8, 8);    // N=512/64,  M=256/32 -> 64 CTAs
    gemm1_kernel<<<grid1, 256>>>(x, W1L, b1L);
    gemm2_kernel<<<grid2, 256>>>(W2L, b2L);
    lstm_kernel<<<128, 896>>>(Wih3, Whh3, b3, Wout, bout, out);
}